// round 14
// baseline (speedup 1.0000x reference)
#include <cuda_runtime.h>
#include <cuda_bf16.h>

// Global accumulators. Zero at load; the winner resets them each run so every
// graph replay sees identical initial state. Counts are exact integers.
__device__ double g_tot = 0.0;
__device__ unsigned int g_cnt = 0u;
__device__ unsigned int g_ticket = 0u;

static constexpr float CX = 0.5f;

__device__ __forceinline__ float warp_red(float v) {
#pragma unroll
    for (int o = 16; o > 0; o >>= 1)
        v += __shfl_down_sync(0xFFFFFFFFu, v, o);
    return v;
}

// One WARP per batch. N = 512 points/batch = 256 float4 / int2 elements.
// Each lane handles 8 stride-32 float4s (16 points) -> 16 independent loads.
// Block = 512 threads = 16 warps = 16 batches; grid = B/16 = 16 blocks.
// (B = 256 is an exact multiple of 16, so every warp maps to a valid batch.)
__global__ void __launch_bounds__(512)
symc_warp_kernel(const float4* __restrict__ kp4,
                 const int2* __restrict__ cls2,
                 float* __restrict__ out) {
    const int t = threadIdx.x;
    const int wid = t >> 5, lane = t & 31;
    const int b = blockIdx.x * 16 + wid;

    __shared__ float stot[16];
    __shared__ unsigned int scnt[16];

    const int base4 = b * 256;  // N/2 float4 per batch

    float4 p[8];
    int2 c[8];
#pragma unroll
    for (int j = 0; j < 8; j++) {
        const int idx = base4 + j * 32 + lane;
        p[j] = kp4[idx];
        c[j] = cls2[idx];
    }

    // 3 symmetric classes: packed counts + 4 float moments each (u = x - cx)
    // counts packed as m0 | m1<<10 | m2<<20 (warp totals <= 512 < 1024).
    unsigned mp = 0u;
    float su0 = 0.f, sq0 = 0.f, sy0 = 0.f, sz0 = 0.f;
    float su1 = 0.f, sq1 = 0.f, sy1 = 0.f, sz1 = 0.f;
    float su2 = 0.f, sq2 = 0.f, sy2 = 0.f, sz2 = 0.f;

#pragma unroll
    for (int j = 0; j < 8; j++) {
        {
            float u = p[j].x - CX, y = p[j].y;
            int cc = c[j].x;
            if (cc == 0)      { mp += 1u;       su0 += u; sq0 += u * u; sy0 += y; sz0 += y * y; }
            else if (cc == 1) { mp += 1u << 10; su1 += u; sq1 += u * u; sy1 += y; sz1 += y * y; }
            else if (cc == 2) { mp += 1u << 20; su2 += u; sq2 += u * u; sy2 += y; sz2 += y * y; }
        }
        {
            float u = p[j].z - CX, y = p[j].w;
            int cc = c[j].y;
            if (cc == 0)      { mp += 1u;       su0 += u; sq0 += u * u; sy0 += y; sz0 += y * y; }
            else if (cc == 1) { mp += 1u << 10; su1 += u; sq1 += u * u; sy1 += y; sz1 += y * y; }
            else if (cc == 2) { mp += 1u << 20; su2 += u; sq2 += u * u; sy2 += y; sz2 += y * y; }
        }
    }

    // Counts: one REDUX. Float moments: shuffle trees.
    mp = __reduce_add_sync(0xFFFFFFFFu, mp);
    su0 = warp_red(su0); sq0 = warp_red(sq0); sy0 = warp_red(sy0); sz0 = warp_red(sz0);
    su1 = warp_red(su1); sq1 = warp_red(sq1); sy1 = warp_red(sy1); sz1 = warp_red(sz1);
    su2 = warp_red(su2); sq2 = warp_red(sq2); sy2 = warp_red(sy2); sz2 = warp_red(sz2);

    if (lane == 0) {
        const unsigned m0 = mp & 0x3FFu;
        const unsigned m1 = (mp >> 10) & 0x3FFu;
        const unsigned m2 = (mp >> 20) & 0x3FFu;
        // Closed form per (batch, class), fp32 (reference sums in fp32 too;
        // worst-case cancellation leaves ~3e-7 rel error, tol is 1e-3):
        //   sum_{i<j} (u_i+u_j)^2 = (m-2)*Su2 + Su^2
        //   sum_{i<j} (y_i-y_j)^2 = m*Sy2 - Sy^2
        //   pairs = m*(m-1)/2  (exact integer)
        float f0 = (float)m0, f1 = (float)m1, f2 = (float)m2;
        float total =
            ((f0 - 2.0f) * sq0 + su0 * su0 + f0 * sz0 - sy0 * sy0)
          + ((f1 - 2.0f) * sq1 + su1 * su1 + f1 * sz1 - sy1 * sy1)
          + ((f2 - 2.0f) * sq2 + su2 * su2 + f2 * sz2 - sy2 * sy2);
        unsigned cnt = (m0 * (m0 - 1u) + m1 * (m1 - 1u) + m2 * (m2 - 1u)) >> 1;
        stot[wid] = total;
        scnt[wid] = cnt;
    }

    __syncthreads();

    if (t == 0) {
        // Pairwise fp32 tree over 16 warp totals; exact integer count sum.
        float t0 = (stot[0] + stot[1]) + (stot[2] + stot[3]);
        float t1 = (stot[4] + stot[5]) + (stot[6] + stot[7]);
        float t2 = (stot[8] + stot[9]) + (stot[10] + stot[11]);
        float t3 = (stot[12] + stot[13]) + (stot[14] + stot[15]);
        float total = (t0 + t1) + (t2 + t3);
        unsigned cnt = 0u;
#pragma unroll
        for (int w = 0; w < 16; w++) cnt += scnt[w];

        atomicAdd(&g_tot, (double)total);
        atomicAdd(&g_cnt, cnt);

        // Single acq_rel ticket: release orders the two atomicAdds above;
        // the winner's acquire pairs with every other block's release.
        unsigned int ticket;
        asm volatile("atom.acq_rel.gpu.add.u32 %0, [%1], 1;"
                     : "=r"(ticket) : "l"(&g_ticket) : "memory");

        if (ticket == gridDim.x - 1) {
            double T = g_tot;
            double C = (double)g_cnt;
            out[0] = (float)(T / (C > 1.0 ? C : 1.0));
            // Reset for the next graph replay (no other writers remain).
            g_tot = 0.0;
            g_cnt = 0u;
            g_ticket = 0u;
        }
    }
}

extern "C" void kernel_launch(void* const* d_in, const int* in_sizes, int n_in,
                              void* d_out, int out_size) {
    const float4* kp4 = (const float4*)d_in[0];  // [B, N, 2] f32
    const int2* cls2 = (const int2*)d_in[1];     // [B, N] i32
    const int N = 512;
    const int B = in_sizes[1] / N;               // 256
    const int grid = (B + 15) / 16;              // 16 batches (warps) per block -> 16

    symc_warp_kernel<<<grid, 512>>>(kp4, cls2, (float*)d_out);
}

// round 15
// speedup vs baseline: 1.3820x; 1.3820x over previous
#include <cuda_runtime.h>
#include <cuda_bf16.h>

// Global accumulators. Zero at load; the winner resets them each run so every
// graph replay sees identical initial state. Counts are exact integers.
__device__ double g_tot = 0.0;
__device__ unsigned int g_cnt = 0u;
__device__ unsigned int g_ticket = 0u;

static constexpr float CX = 0.5f;

__device__ __forceinline__ float warp_red(float v) {
#pragma unroll
    for (int o = 16; o > 0; o >>= 1)
        v += __shfl_down_sync(0xFFFFFFFFu, v, o);
    return v;
}

// One WARP per batch. N = 512 points/batch = 256 float4 / int2 elements.
// Each lane handles 8 stride-32 float4s (16 points) -> 16 independent loads.
// Block = 512 threads = 16 warps = 16 batches; grid = B/16 = 16 blocks.
// (B = 256 is an exact multiple of 16, so every warp maps to a valid batch.)
__global__ void __launch_bounds__(512)
symc_warp_kernel(const float4* __restrict__ kp4,
                 const int2* __restrict__ cls2,
                 float* __restrict__ out) {
    const int t = threadIdx.x;
    const int wid = t >> 5, lane = t & 31;
    const int b = blockIdx.x * 16 + wid;

    __shared__ float stot[16];
    __shared__ unsigned int scnt[16];

    const int base4 = b * 256;  // N/2 float4 per batch

    float4 p[8];
    int2 c[8];
#pragma unroll
    for (int j = 0; j < 8; j++) {
        const int idx = base4 + j * 32 + lane;
        p[j] = kp4[idx];
        c[j] = cls2[idx];
    }

    // 3 symmetric classes: packed counts + 4 float moments each (u = x - cx)
    // counts packed as m0 | m1<<10 | m2<<20 (warp totals <= 512 < 1024).
    unsigned mp = 0u;
    float su0 = 0.f, sq0 = 0.f, sy0 = 0.f, sz0 = 0.f;
    float su1 = 0.f, sq1 = 0.f, sy1 = 0.f, sz1 = 0.f;
    float su2 = 0.f, sq2 = 0.f, sy2 = 0.f, sz2 = 0.f;

#pragma unroll
    for (int j = 0; j < 8; j++) {
        {
            float u = p[j].x - CX, y = p[j].y;
            int cc = c[j].x;
            if (cc == 0)      { mp += 1u;       su0 += u; sq0 += u * u; sy0 += y; sz0 += y * y; }
            else if (cc == 1) { mp += 1u << 10; su1 += u; sq1 += u * u; sy1 += y; sz1 += y * y; }
            else if (cc == 2) { mp += 1u << 20; su2 += u; sq2 += u * u; sy2 += y; sz2 += y * y; }
        }
        {
            float u = p[j].z - CX, y = p[j].w;
            int cc = c[j].y;
            if (cc == 0)      { mp += 1u;       su0 += u; sq0 += u * u; sy0 += y; sz0 += y * y; }
            else if (cc == 1) { mp += 1u << 10; su1 += u; sq1 += u * u; sy1 += y; sz1 += y * y; }
            else if (cc == 2) { mp += 1u << 20; su2 += u; sq2 += u * u; sy2 += y; sz2 += y * y; }
        }
    }

    // Counts: one REDUX. Float moments: shuffle trees.
    mp = __reduce_add_sync(0xFFFFFFFFu, mp);
    su0 = warp_red(su0); sq0 = warp_red(sq0); sy0 = warp_red(sy0); sz0 = warp_red(sz0);
    su1 = warp_red(su1); sq1 = warp_red(sq1); sy1 = warp_red(sy1); sz1 = warp_red(sz1);
    su2 = warp_red(su2); sq2 = warp_red(sq2); sy2 = warp_red(sy2); sz2 = warp_red(sz2);

    if (lane == 0) {
        const unsigned m0 = mp & 0x3FFu;
        const unsigned m1 = (mp >> 10) & 0x3FFu;
        const unsigned m2 = (mp >> 20) & 0x3FFu;
        // Closed form per (batch, class), fp32 (reference sums in fp32 too;
        // worst-case cancellation leaves ~3e-7 rel error, tol is 1e-3):
        //   sum_{i<j} (u_i+u_j)^2 = (m-2)*Su2 + Su^2
        //   sum_{i<j} (y_i-y_j)^2 = m*Sy2 - Sy^2
        //   pairs = m*(m-1)/2  (exact integer)
        float f0 = (float)m0, f1 = (float)m1, f2 = (float)m2;
        float total =
            ((f0 - 2.0f) * sq0 + su0 * su0 + f0 * sz0 - sy0 * sy0)
          + ((f1 - 2.0f) * sq1 + su1 * su1 + f1 * sz1 - sy1 * sy1)
          + ((f2 - 2.0f) * sq2 + su2 * su2 + f2 * sz2 - sy2 * sy2);
        unsigned cnt = (m0 * (m0 - 1u) + m1 * (m1 - 1u) + m2 * (m2 - 1u)) >> 1;
        stot[wid] = total;
        scnt[wid] = cnt;
    }

    __syncthreads();

    if (t == 0) {
        // Pairwise fp32 tree over 16 warp totals; exact integer count sum.
        float t0 = (stot[0] + stot[1]) + (stot[2] + stot[3]);
        float t1 = (stot[4] + stot[5]) + (stot[6] + stot[7]);
        float t2 = (stot[8] + stot[9]) + (stot[10] + stot[11]);
        float t3 = (stot[12] + stot[13]) + (stot[14] + stot[15]);
        float total = (t0 + t1) + (t2 + t3);
        unsigned cnt = 0u;
#pragma unroll
        for (int w = 0; w < 16; w++) cnt += scnt[w];

        atomicAdd(&g_tot, (double)total);
        atomicAdd(&g_cnt, cnt);

        // Single acq_rel ticket: release orders the two atomicAdds above;
        // the winner's acquire pairs with every other block's release.
        unsigned int ticket;
        asm volatile("atom.acq_rel.gpu.add.u32 %0, [%1], 1;"
                     : "=r"(ticket) : "l"(&g_ticket) : "memory");

        if (ticket == gridDim.x - 1) {
            double T = g_tot;
            double C = (double)g_cnt;
            out[0] = (float)(T / (C > 1.0 ? C : 1.0));
            // Reset for the next graph replay (no other writers remain).
            g_tot = 0.0;
            g_cnt = 0u;
            g_ticket = 0u;
        }
    }
}

extern "C" void kernel_launch(void* const* d_in, const int* in_sizes, int n_in,
                              void* d_out, int out_size) {
    const float4* kp4 = (const float4*)d_in[0];  // [B, N, 2] f32
    const int2* cls2 = (const int2*)d_in[1];     // [B, N] i32
    const int N = 512;
    const int B = in_sizes[1] / N;               // 256
    const int grid = (B + 15) / 16;              // 16 batches (warps) per block -> 16

    symc_warp_kernel<<<grid, 512>>>(kp4, cls2, (float*)d_out);
}